// round 10
// baseline (speedup 1.0000x reference)
#include <cuda_runtime.h>
#include <mma.h>
#include <math.h>
#include <cstdint>

using namespace nvcuda;

// Problem constants
constexpr int cNB   = 512;
constexpr int cMS   = 8;
constexpr int cT    = 64;
constexpr int cIN   = 360;
constexpr int cH    = 230;
constexpr int cOUT  = 53;
constexpr int cENT  = 8;
constexpr int cB    = cNB * cMS;     // 4096
constexpr int c3H   = 3 * cH;        // 690
constexpr int c2H   = 2 * cH;        // 460
constexpr size_t cTB = (size_t)cT * cB;   // 262144

constexpr int cGP   = 240;           // per-gate padded width in g_Wt
constexpr int cNW   = 3 * cGP;       // 720 (g_Wt n-dim)
constexpr int cKP   = 256;           // padded K (hidden) -> 8 chunks of 32
constexpr int BT    = 64;            // batch tile per GRU CTA
constexpr int cHSx  = 260;           // hex smem row stride (256 data + 4)
constexpr int cWS2  = 388;           // staged W row stride (384 data + 4)

// ---------------------------------------------------------------------------
// Scratch
// ---------------------------------------------------------------------------
static __device__ float g_xg_f[(size_t)cT * cB * c3H];  // [T][B][3H]
static __device__ float g_xg_r[(size_t)cT * cB * c3H];
static __device__ float g_out [(size_t)cT * cB * c2H];  // [T][B][2H]
static __device__ float g_Wt  [2][(size_t)cKP * cNW];   // k-major padded tf32 W_hh
static __device__ float g_Wih [2][(size_t)c3H * cIN];   // tf32 W_ih
static __device__ float g_Wwc [(size_t)c2H * c2H];      // tf32 W_word
static __device__ float g_Wsc [(size_t)c2H * c2H];      // tf32 W_sent
static __device__ float g_scorep[(size_t)cTB * 8];      // word-score partials
static __device__ float g_alpha[(size_t)cB * cT];
static __device__ float g_wv  [(size_t)cB * c2H];
static __device__ float g_u2  [(size_t)cB * c2H];
static __device__ float g_s2  [cB];
static __device__ float g_sent[(size_t)cNB * c2H];

// ---------------------------------------------------------------------------
// Helpers
// ---------------------------------------------------------------------------
__device__ __forceinline__ float to_tf32(float x) {
    float r;
    asm("cvt.rna.tf32.f32 %0, %1;\n" : "=f"(r) : "f"(x));
    return r;
}
__device__ __forceinline__ float sigmoidf(float x) {
    return 1.f / (1.f + expf(-x));
}
__device__ __forceinline__ unsigned int smem_u32(const void* p) {
    return (unsigned int)__cvta_generic_to_shared(p);
}
__device__ __forceinline__ void cp16(unsigned int d, const void* s, int srcsize) {
    asm volatile("cp.async.cg.shared.global [%0], [%1], 16, %2;\n"
                 :: "r"(d), "l"(s), "r"(srcsize));
}
__device__ __forceinline__ void cp_commit() {
    asm volatile("cp.async.commit_group;\n");
}
template <int N>
__device__ __forceinline__ void cp_wait() {
    asm volatile("cp.async.wait_group %0;\n" :: "n"(N));
}
__device__ __forceinline__ void l2_prefetch(const void* p) {
    asm volatile("prefetch.global.L2 [%0];" :: "l"(p));
}

typedef wmma::fragment<wmma::matrix_a, 16, 16, 8, wmma::precision::tf32, wmma::row_major> FragA;
typedef wmma::fragment<wmma::matrix_b, 16, 16, 8, wmma::precision::tf32, wmma::col_major> FragBc;
typedef wmma::fragment<wmma::matrix_b, 16, 16, 8, wmma::precision::tf32, wmma::row_major> FragBr;
typedef wmma::fragment<wmma::accumulator, 16, 16, 8, float> FragC;

template <class F>
__device__ __forceinline__ void cvt_frag(F& f) {
    #pragma unroll
    for (int i = 0; i < f.num_elements; i++) f.x[i] = to_tf32(f.x[i]);
}

// ---------------------------------------------------------------------------
// Prep / utility kernels
// ---------------------------------------------------------------------------
__global__ void zero_out_kernel(float* p, int n) {
    int i = blockIdx.x * blockDim.x + threadIdx.x;
    if (i < n) p[i] = 0.f;
}

// tf32 rounding copy into a DEVICE-SELECTED destination global.
// (Device symbols must not be referenced from host code.)
__global__ void tf32_prep_kernel(const float* __restrict__ src, int which, int n) {
    int i = blockIdx.x * blockDim.x + threadIdx.x;
    if (i >= n) return;
    float v = to_tf32(src[i]);
    if      (which == 0) g_Wih[0][i] = v;
    else if (which == 1) g_Wih[1][i] = v;
    else if (which == 2) g_Wwc[i]    = v;
    else                 g_Wsc[i]    = v;
}

// g_Wt[dir][k][g*240 + j] = tf32(Whh[g*230 + j][k]); zero padding elsewhere.
__global__ void wt_prep_kernel(const float* __restrict__ Whhf,
                               const float* __restrict__ Whhr) {
    int i = blockIdx.x * blockDim.x + threadIdx.x;
    if (i >= 2 * cKP * cNW) return;
    int dir = i / (cKP * cNW);
    int r = i % (cKP * cNW);
    int k = r / cNW, n = r % cNW;
    int g = n / cGP, j = n % cGP;
    const float* W = dir ? Whhr : Whhf;
    float v = 0.f;
    if (j < cH && k < cH) v = to_tf32(W[(size_t)(g * cH + j) * cH + k]);
    g_Wt[dir][(size_t)k * cNW + n] = v;
}

// ---------------------------------------------------------------------------
// Input projection: C[M=262144, N=690] = bag @ W^T + b  (TN), row remap.
// B operand pre-rounded to tf32 (g_Wih) -> no cvt on B frags.
// ---------------------------------------------------------------------------
__global__ void __launch_bounds__(256, 2) iproj_kernel(
    const float* __restrict__ bag,
    const float* __restrict__ bf, const float* __restrict__ br)
{
    const int z = blockIdx.z;
    const float* __restrict__ W    = g_Wih[z];
    const float* __restrict__ bias = z ? br : bf;
    float* __restrict__ dst        = z ? g_xg_r : g_xg_f;

    extern __shared__ float sm[];
    float* As = sm;            // [2][128][36]
    float* Bs = sm + 9216;     // [2][64][36]
    float* Cs = sm;            // [128][68]

    const int n0 = blockIdx.x * 64;
    const int m0 = blockIdx.y * 128;
    const int tid = threadIdx.x;
    const int wid = tid >> 5;
    const int wm = wid & 3;
    const int wn = wid >> 2;

    constexpr int KT = (cIN + 31) / 32;   // 12

    FragC acc[2][2];
    #pragma unroll
    for (int i = 0; i < 2; i++)
        #pragma unroll
        for (int j = 0; j < 2; j++) wmma::fill_fragment(acc[i][j], 0.f);

    auto load_stage = [&](int st, int k0) {
        float* A = As + st * 4608;
        float* B = Bs + st * 2304;
        #pragma unroll
        for (int q = 0; q < 4; q++) {
            int idx = q * 256 + tid;
            int r = idx >> 3, c4 = idx & 7;
            int k = k0 + c4 * 4;
            cp16(smem_u32(&A[r * 36 + c4 * 4]),
                 bag + (size_t)(m0 + r) * cIN + min(k, cIN - 4),
                 (k + 4 <= cIN) ? 16 : 0);
        }
        #pragma unroll
        for (int q = 0; q < 2; q++) {
            int idx = q * 256 + tid;
            int n = idx >> 3, c4 = idx & 7;
            int k = k0 + c4 * 4;
            int nn = min(n0 + n, c3H - 1);
            cp16(smem_u32(&B[n * 36 + c4 * 4]),
                 W + (size_t)nn * cIN + min(k, cIN - 4),
                 (n0 + n < c3H && k + 4 <= cIN) ? 16 : 0);
        }
    };

    load_stage(0, 0);
    cp_commit();

    for (int kt = 0; kt < KT; kt++) {
        if (kt + 1 < KT) {
            load_stage((kt + 1) & 1, (kt + 1) * 32);
            cp_commit();
            cp_wait<1>();
        } else {
            cp_wait<0>();
        }
        __syncthreads();
        float* A = As + (kt & 1) * 4608;
        float* B = Bs + (kt & 1) * 2304;
        #pragma unroll
        for (int kk = 0; kk < 32; kk += 8) {
            FragA a0, a1; FragBc b0, b1;
            wmma::load_matrix_sync(a0, &A[(wm * 32) * 36 + kk], 36);
            wmma::load_matrix_sync(a1, &A[(wm * 32 + 16) * 36 + kk], 36);
            wmma::load_matrix_sync(b0, &B[(wn * 32) * 36 + kk], 36);
            wmma::load_matrix_sync(b1, &B[(wn * 32 + 16) * 36 + kk], 36);
            cvt_frag(a0); cvt_frag(a1);
            wmma::mma_sync(acc[0][0], a0, b0, acc[0][0]);
            wmma::mma_sync(acc[0][1], a0, b1, acc[0][1]);
            wmma::mma_sync(acc[1][0], a1, b0, acc[1][0]);
            wmma::mma_sync(acc[1][1], a1, b1, acc[1][1]);
        }
        __syncthreads();
    }

    #pragma unroll
    for (int i = 0; i < 2; i++)
        #pragma unroll
        for (int j = 0; j < 2; j++)
            wmma::store_matrix_sync(&Cs[(wm * 32 + i * 16) * 68 + wn * 32 + j * 16],
                                    acc[i][j], 68, wmma::mem_row_major);
    __syncthreads();

    #pragma unroll
    for (int q = 0; q < 32; q++) {
        int idx = q * 256 + tid;
        int r = idx >> 6, c = idx & 63;
        int n = n0 + c;
        if (n < c3H) {
            int m = m0 + r;
            size_t crow = (size_t)(m & (cT - 1)) * cB + (m >> 6);
            dst[crow * c3H + n] = Cs[r * 68 + c] + bias[n];
        }
    }
}

// ---------------------------------------------------------------------------
// Attention GEMM (NN). N=K=460, pre-tf32 B.
//  SEL 2: A=g_out, fused epilogue: score partials -> g_scorep (no u stored)
//  SEL 3: A=g_wv,  epilogue: u2 = tanh(...) -> g_u2
// ---------------------------------------------------------------------------
template <int SEL>
__global__ void __launch_bounds__(256, 2) attn_gemm_kernel(
    const float* __restrict__ bias, const float* __restrict__ pj)
{
    const float* __restrict__ A  = (SEL == 2) ? g_out : g_wv;
    const float* __restrict__ Bw = (SEL == 2) ? g_Wwc : g_Wsc;
    constexpr int N = c2H, K = c2H;

    extern __shared__ float sm[];
    float* As = sm;            // [2][128][36]
    float* Bs = sm + 9216;     // [2][32][68]
    float* Cs = sm;            // [128][68]

    const int n0 = blockIdx.x * 64;
    const int m0 = blockIdx.y * 128;
    const int tid = threadIdx.x;
    const int wid = tid >> 5;
    const int lane = tid & 31;
    const int wm = wid & 3;
    const int wn = wid >> 2;

    constexpr int KT = (K + 31) / 32;   // 15

    FragC acc[2][2];
    #pragma unroll
    for (int i = 0; i < 2; i++)
        #pragma unroll
        for (int j = 0; j < 2; j++) wmma::fill_fragment(acc[i][j], 0.f);

    auto load_stage = [&](int st, int k0) {
        float* Ab = As + st * 4608;
        float* Bb = Bs + st * 2176;
        #pragma unroll
        for (int q = 0; q < 4; q++) {
            int idx = q * 256 + tid;
            int r = idx >> 3, c4 = idx & 7;
            int k = k0 + c4 * 4;
            cp16(smem_u32(&Ab[r * 36 + c4 * 4]),
                 A + (size_t)(m0 + r) * K + min(k, K - 4),
                 (k + 4 <= K) ? 16 : 0);
        }
        #pragma unroll
        for (int q = 0; q < 2; q++) {
            int idx = q * 256 + tid;
            int k = idx >> 4, n4 = idx & 15;
            int kk = k0 + k;
            int n = n0 + n4 * 4;
            cp16(smem_u32(&Bb[k * 68 + n4 * 4]),
                 Bw + (size_t)min(kk, K - 1) * N + min(n, N - 4),
                 (kk < K && n + 4 <= N) ? 16 : 0);
        }
    };

    load_stage(0, 0);
    cp_commit();

    for (int kt = 0; kt < KT; kt++) {
        if (kt + 1 < KT) {
            load_stage((kt + 1) & 1, (kt + 1) * 32);
            cp_commit();
            cp_wait<1>();
        } else {
            cp_wait<0>();
        }
        __syncthreads();
        float* Ab = As + (kt & 1) * 4608;
        float* Bb = Bs + (kt & 1) * 2176;
        #pragma unroll
        for (int kk = 0; kk < 32; kk += 8) {
            FragA a0, a1; FragBr b0, b1;
            wmma::load_matrix_sync(a0, &Ab[(wm * 32) * 36 + kk], 36);
            wmma::load_matrix_sync(a1, &Ab[(wm * 32 + 16) * 36 + kk], 36);
            wmma::load_matrix_sync(b0, &Bb[kk * 68 + wn * 32], 68);
            wmma::load_matrix_sync(b1, &Bb[kk * 68 + wn * 32 + 16], 68);
            cvt_frag(a0); cvt_frag(a1);
            wmma::mma_sync(acc[0][0], a0, b0, acc[0][0]);
            wmma::mma_sync(acc[0][1], a0, b1, acc[0][1]);
            wmma::mma_sync(acc[1][0], a1, b0, acc[1][0]);
            wmma::mma_sync(acc[1][1], a1, b1, acc[1][1]);
        }
        __syncthreads();
    }

    #pragma unroll
    for (int i = 0; i < 2; i++)
        #pragma unroll
        for (int j = 0; j < 2; j++)
            wmma::store_matrix_sync(&Cs[(wm * 32 + i * 16) * 68 + wn * 32 + j * 16],
                                    acc[i][j], 68, wmma::mem_row_major);
    __syncthreads();

    if (SEL == 2) {
        // fused: score partial over this n-tile; u never stored.
        #pragma unroll
        for (int rr = 0; rr < 16; rr++) {
            int row = wid * 16 + rr;
            int n1 = n0 + lane, n2 = n0 + lane + 32;
            float v = 0.f;
            if (n1 < N) v += tanhf(Cs[row * 68 + lane] + bias[n1]) * pj[n1];
            if (n2 < N) v += tanhf(Cs[row * 68 + lane + 32] + bias[n2]) * pj[n2];
            #pragma unroll
            for (int o = 16; o; o >>= 1) v += __shfl_xor_sync(0xffffffffu, v, o);
            if (lane == 0)
                g_scorep[(size_t)(m0 + row) * 8 + blockIdx.x] = v;
        }
    } else {
        #pragma unroll
        for (int q = 0; q < 32; q++) {
            int idx = q * 256 + tid;
            int r = idx >> 6, c = idx & 63;
            int n = n0 + c;
            if (n < N)
                g_u2[(size_t)(m0 + r) * N + n] = tanhf(Cs[r * 68 + c] + bias[n]);
        }
    }
}

// ---------------------------------------------------------------------------
// Persistent GRU v4: one CTA per (64-batch tile, dir), 128 CTAs = one wave.
// K padded to 256 -> 8 chunks of 32 per pass (2 passes over j).
// 3-buffer cp.async, ONE barrier per chunk. hex holds exact h; A-frags cvt
// to tf32 on load. Pass-0 epilogue defers h-writes via g_out; read back
// after pass 1 (both passes must see h(t-1) in hex during their mma).
// ---------------------------------------------------------------------------
constexpr int WBUF      = 32 * cWS2;            // 12416 floats per buffer
constexpr int GRU_HEX   = BT * cHSx;            // 16640 floats
constexpr int GRU_SMEMF = GRU_HEX + 3 * WBUF;   // 53888 floats
constexpr int GRU_SMEM  = GRU_SMEMF * 4;        // 215552 bytes

__global__ void __launch_bounds__(256, 1) gru_persistent_kernel(
    const float* __restrict__ bhh_f, const float* __restrict__ bhh_r)
{
    const int dir = blockIdx.y;
    const int b0 = blockIdx.x * BT;
    const float* __restrict__ xg  = dir ? g_xg_r : g_xg_f;
    const float* __restrict__ bhh = dir ? bhh_r : bhh_f;
    const float* __restrict__ Wd  = g_Wt[dir];

    extern __shared__ float sm[];
    float* hex = sm;                 // [64][260] exact h (k-pad zeros)
    float* Wst = sm + GRU_HEX;       // [3][32][388]
    const int tid = threadIdx.x;
    const int wid = tid >> 5;
    const int lane = tid & 31;
    float* slab = Wst + wid * 832;   // aliases buffer 0 (used only post-chunks)

    for (int i = tid; i < GRU_HEX; i += 256) hex[i] = 0.f;
    __syncthreads();

    // stage chunk (32 k-rows x pass-p 384 cols) into buffer buf
    auto stage = [&](int buf, int p, int chunk) {
        float* dstW = Wst + buf * WBUF;
        const float* src = Wd + (size_t)(chunk * 32) * cNW;
        #pragma unroll
        for (int q = 0; q < 12; q++) {
            int idx = q * 256 + tid;          // < 3072
            int r = idx / 96;
            int rem = idx - r * 96;
            int g = rem >> 5;
            int rem2 = rem & 31;
            int w = rem2 >> 2;
            int c4 = rem2 & 3;
            int jt = 2 * w + p;
            cp16(smem_u32(&dstW[r * cWS2 + g * 128 + w * 16 + c4 * 4]),
                 src + (size_t)r * cNW + g * cGP + min(jt, 14) * 16 + c4 * 4,
                 (jt < 15) ? 16 : 0);
        }
    };

    for (int s = 0; s < cT; s++) {
        const int t = dir ? (cT - 1 - s) : s;

        // L2-prefetch this step's xg rows (epilogue consumes later)
        {
            const float* base = xg + ((size_t)t * cB + b0) * c3H;
            #pragma unroll
            for (int q = 0; q < 6; q++) {
                int line = q * 256 + tid;
                if (line < 1408) {
                    int r = line / 22, c = line % 22;
                    int off = c * 32;
                    if (off < c3H) l2_prefetch(base + (size_t)r * c3H + off);
                }
            }
        }

        for (int p = 0; p < 2; p++) {
            const int jt = 2 * wid + p;

            FragC acc[3][4];
            #pragma unroll
            for (int g = 0; g < 3; g++)
                #pragma unroll
                for (int m = 0; m < 4; m++) wmma::fill_fragment(acc[g][m], 0.f);

            stage(0, p, 0); cp_commit();
            stage(1, p, 1); cp_commit();

            for (int c = 0; c < 8; c++) {
                if (c + 2 < 8) cp_wait<1>(); else cp_wait<0>();
                __syncthreads();                       // data ready + prev readers done
                if (c + 2 < 8) { stage((c + 2) % 3, p, c + 2); cp_commit(); }

                if (jt < 15) {
                    float* Wb = Wst + (c % 3) * WBUF;
                    const int kb = c * 32;
                    #pragma unroll
                    for (int ks = 0; ks < 4; ks++) {
                        FragBr bf[3];
                        #pragma unroll
                        for (int g = 0; g < 3; g++)
                            wmma::load_matrix_sync(bf[g],
                                Wb + (ks * 8) * cWS2 + g * 128 + wid * 16, cWS2);
                        #pragma unroll
                        for (int m = 0; m < 4; m++) {
                            FragA af;
                            wmma::load_matrix_sync(af,
                                hex + (m * 16) * cHSx + kb + ks * 8, cHSx);
                            cvt_frag(af);
                            #pragma unroll
                            for (int g = 0; g < 3; g++)
                                wmma::mma_sync(acc[g][m], af, bf[g], acc[g][m]);
                        }
                    }
                }
            }
            __syncthreads();   // all chunk compute done before slab (buf0) reuse

            // gate epilogue (pass 0: defer h-writes via g_out; pass 1: write hex)
            if (jt < 15) {
                #pragma unroll
                for (int m = 0; m < 4; m++) {
                    wmma::store_matrix_sync(slab +  0, acc[0][m], 52, wmma::mem_row_major);
                    wmma::store_matrix_sync(slab + 16, acc[1][m], 52, wmma::mem_row_major);
                    wmma::store_matrix_sync(slab + 32, acc[2][m], 52, wmma::mem_row_major);
                    __syncwarp();
                    #pragma unroll
                    for (int e = 0; e < 8; e++) {
                        int idx = e * 32 + lane;
                        int rr = idx >> 4, cc = idx & 15;
                        int j = jt * 16 + cc;
                        if (j < cH) {
                            int bl = m * 16 + rr;
                            int b = b0 + bl;
                            const float* xrow = xg + ((size_t)t * cB + b) * c3H;
                            float hgr = slab[rr * 52 + cc];
                            float hgz = slab[rr * 52 + 16 + cc];
                            float hgn = slab[rr * 52 + 32 + cc];
                            float r = sigmoidf(xrow[j]          + hgr + bhh[j]);
                            float z = sigmoidf(xrow[cH + j]     + hgz + bhh[cH + j]);
                            float n = tanhf(xrow[2 * cH + j] + r * (hgn + bhh[2 * cH + j]));
                            float hold = hex[bl * cHSx + j];
                            float h2 = (1.f - z) * n + z * hold;
                            if (p == 1) hex[bl * cHSx + j] = h2;
                            g_out[((size_t)t * cB + b) * c2H + dir * cH + j] = h2;
                        }
                    }
                    __syncwarp();
                }
            }
            __syncthreads();   // epilogue done before next pass staging
        }

        // read back even-j h(t) from g_out into hex (pass-0's deferred writes)
        #pragma unroll
        for (int q = 0; q < 32; q++) {
            int e = q * 256 + tid;           // < 8192
            int bl = e >> 7;
            int jj = e & 127;
            int j = ((jj >> 4) << 5) + (jj & 15);   // even j-tiles
            if (j < cH)
                hex[bl * cHSx + j] =
                    g_out[((size_t)t * cB + (b0 + bl)) * c2H + dir * cH + j];
        }
        __syncthreads();
    }
}

// ---------------------------------------------------------------------------
// small kernels
// ---------------------------------------------------------------------------
__global__ void rowdot_sent_kernel(const float* __restrict__ proj) {
    int row = blockIdx.x * 8 + (threadIdx.x >> 5);
    if (row >= cB) return;
    int lane = threadIdx.x & 31;
    const float* u = g_u2 + (size_t)row * c2H;
    float s = 0.f;
    for (int j = lane; j < c2H; j += 32) s += u[j] * proj[j];
    #pragma unroll
    for (int o = 16; o; o >>= 1) s += __shfl_xor_sync(0xffffffffu, s, o);
    if (lane == 0) g_s2[row] = s;
}

// softmax over T per batch element (warp per b); sums 8 score partials per (t,b)
__global__ void softmaxT_kernel() {
    int b = blockIdx.x * 8 + (threadIdx.x >> 5);
    int lane = threadIdx.x & 31;
    const float* p0 = g_scorep + ((size_t)lane * cB + b) * 8;
    const float* p1 = g_scorep + ((size_t)(lane + 32) * cB + b) * 8;
    float v0 = 0.f, v1 = 0.f;
    #pragma unroll
    for (int i = 0; i < 8; i++) { v0 += p0[i]; v1 += p1[i]; }
    float m = fmaxf(v0, v1);
    #pragma unroll
    for (int o = 16; o; o >>= 1) m = fmaxf(m, __shfl_xor_sync(0xffffffffu, m, o));
    float e0 = expf(v0 - m), e1 = expf(v1 - m);
    float sum = e0 + e1;
    #pragma unroll
    for (int o = 16; o; o >>= 1) sum += __shfl_xor_sync(0xffffffffu, sum, o);
    float inv = 1.f / sum;
    g_alpha[(size_t)b * cT + lane] = e0 * inv;
    g_alpha[(size_t)b * cT + lane + 32] = e1 * inv;
}

__global__ void wordvec_kernel() {
    int b = blockIdx.y;
    int h = blockIdx.x * 128 + threadIdx.x;
    if (h >= c2H) return;
    const float* al = g_alpha + (size_t)b * cT;
    float s = 0.f;
    for (int t = 0; t < cT; t++)
        s += al[t] * g_out[((size_t)t * cB + b) * c2H + h];
    g_wv[(size_t)b * c2H + h] = s;
}

__global__ void sentvec_kernel() {
    int nb = blockIdx.x;
    __shared__ float beta[cMS];
    if (threadIdx.x == 0) {
        float v[cMS];
        float m = -1e30f;
        for (int ms = 0; ms < cMS; ms++) { v[ms] = g_s2[nb * cMS + ms]; m = fmaxf(m, v[ms]); }
        float sum = 0.f;
        for (int ms = 0; ms < cMS; ms++) { v[ms] = expf(v[ms] - m); sum += v[ms]; }
        float inv = 1.f / sum;
        for (int ms = 0; ms < cMS; ms++) beta[ms] = v[ms] * inv;
    }
    __syncthreads();
    for (int h = threadIdx.x; h < c2H; h += blockDim.x) {
        float s = 0.f;
        #pragma unroll
        for (int ms = 0; ms < cMS; ms++)
            s += beta[ms] * g_wv[((size_t)nb * cMS + ms) * c2H + h];
        g_sent[(size_t)nb * c2H + h] = s;
    }
}

__global__ void fc_scatter_kernel(const float* __restrict__ fcW,
                                  const float* __restrict__ fcb,
                                  const int* __restrict__ pairs,
                                  float* __restrict__ out)
{
    int nb = blockIdx.x;
    __shared__ float sv[c2H];
    for (int k = threadIdx.x; k < c2H; k += blockDim.x)
        sv[k] = g_sent[(size_t)nb * c2H + k];
    __syncthreads();
    int o = threadIdx.x;
    if (o < cOUT) {
        const float* w = fcW + (size_t)o * c2H;
        float s = fcb[o];
        for (int k = 0; k < c2H; k++) s += sv[k] * w[k];
        int d  = pairs[nb * 3 + 0];
        int e1 = pairs[nb * 3 + 1];
        int e2 = pairs[nb * 3 + 2];
        out[(((size_t)d * cENT + e1) * cENT + e2) * cOUT + o] = s;
    }
}

// ---------------------------------------------------------------------------
extern "C" void kernel_launch(void* const* d_in, const int* in_sizes, int n_in,
                              void* d_out, int out_size) {
    const float* bag   = (const float*)d_in[0];
    const float* Wihf  = (const float*)d_in[1];
    const float* Whhf  = (const float*)d_in[2];
    const float* bihf  = (const float*)d_in[3];
    const float* bhhf  = (const float*)d_in[4];
    const float* Wihr  = (const float*)d_in[5];
    const float* Whhr  = (const float*)d_in[6];
    const float* bihr  = (const float*)d_in[7];
    const float* bhhr  = (const float*)d_in[8];
    const float* Wword = (const float*)d_in[9];
    const float* bword = (const float*)d_in[10];
    const float* pjw   = (const float*)d_in[11];
    const float* Wsent = (const float*)d_in[12];
    const float* bsent = (const float*)d_in[13];
    const float* pjs   = (const float*)d_in[14];
    const float* fcW   = (const float*)d_in[15];
    const float* fcb   = (const float*)d_in[16];
    const int*   pairs = (const int*)d_in[17];
    float* out = (float*)d_out;

    constexpr int smem_iproj = (2 * 128 * 36 + 2 * 64 * 36) * 4;   // 55296
    constexpr int smem_attn  = (2 * 128 * 36 + 2 * 32 * 68) * 4;   // 54272

    static int attr_done = 0;
    if (!attr_done) {
        cudaFuncSetAttribute(iproj_kernel, cudaFuncAttributeMaxDynamicSharedMemorySize, smem_iproj);
        cudaFuncSetAttribute(attn_gemm_kernel<2>, cudaFuncAttributeMaxDynamicSharedMemorySize, smem_attn);
        cudaFuncSetAttribute(attn_gemm_kernel<3>, cudaFuncAttributeMaxDynamicSharedMemorySize, smem_attn);
        cudaFuncSetAttribute(gru_persistent_kernel, cudaFuncAttributeMaxDynamicSharedMemorySize, GRU_SMEM);
        attr_done = 1;
    }

    zero_out_kernel<<<(out_size + 255) / 256, 256>>>(out, out_size);
    wt_prep_kernel<<<(2 * cKP * cNW + 255) / 256, 256>>>(Whhf, Whhr);
    tf32_prep_kernel<<<(c3H * cIN + 255) / 256, 256>>>(Wihf, 0, c3H * cIN);
    tf32_prep_kernel<<<(c3H * cIN + 255) / 256, 256>>>(Wihr, 1, c3H * cIN);
    tf32_prep_kernel<<<(c2H * c2H + 255) / 256, 256>>>(Wword, 2, c2H * c2H);
    tf32_prep_kernel<<<(c2H * c2H + 255) / 256, 256>>>(Wsent, 3, c2H * c2H);

    // input projections (both dirs)
    {
        dim3 grid((c3H + 63) / 64, (int)(cTB / 128), 2);
        iproj_kernel<<<grid, 256, smem_iproj>>>(bag, bihf, bihr);
    }

    // GRU recurrence: single persistent launch, 128 CTAs = one wave
    {
        dim3 grid(cB / BT, 2);
        gru_persistent_kernel<<<grid, 256, GRU_SMEM>>>(bhhf, bhhr);
    }

    // word attention (scores fused; no u materialized)
    {
        dim3 grid((c2H + 63) / 64, (int)(cTB / 128));
        attn_gemm_kernel<2><<<grid, 256, smem_attn>>>(bword, pjw);
    }
    softmaxT_kernel<<<cB / 8, 256>>>();
    {
        dim3 grid((c2H + 127) / 128, cB);
        wordvec_kernel<<<grid, 128>>>();
    }

    // sentence attention
    {
        dim3 grid((c2H + 63) / 64, cB / 128);
        attn_gemm_kernel<3><<<grid, 256, smem_attn>>>(bsent, nullptr);
    }
    rowdot_sent_kernel<<<cB / 8, 256>>>(pjs);
    sentvec_kernel<<<cNB, 128>>>();

    fc_scatter_kernel<<<cNB, 64>>>(fcW, fcb, pairs, out);
}

// round 11
// speedup vs baseline: 1.1088x; 1.1088x over previous
#include <cuda_runtime.h>
#include <mma.h>
#include <math.h>
#include <cstdint>

using namespace nvcuda;

// Problem constants
constexpr int cNB   = 512;
constexpr int cMS   = 8;
constexpr int cT    = 64;
constexpr int cIN   = 360;
constexpr int cH    = 230;
constexpr int cOUT  = 53;
constexpr int cENT  = 8;
constexpr int cB    = cNB * cMS;     // 4096
constexpr int c3H   = 3 * cH;        // 690
constexpr int c2H   = 2 * cH;        // 460
constexpr size_t cTB = (size_t)cT * cB;   // 262144

constexpr int cGP   = 240;           // per-gate padded width in g_Wt
constexpr int cNW   = 3 * cGP;       // 720 (g_Wt n-dim)
constexpr int cKW   = 232;           // Wt k-rows (hidden padded to 8)
constexpr int BT    = 64;            // batch tile per GRU CTA
constexpr int cHS   = 236;           // hs/hex smem row stride
constexpr int cWS   = 724;           // GRU W stage row stride

// ---------------------------------------------------------------------------
// Scratch
// ---------------------------------------------------------------------------
static __device__ float g_xg_f[(size_t)cT * cB * c3H];  // [T][B][3H]
static __device__ float g_xg_r[(size_t)cT * cB * c3H];
static __device__ float g_out [(size_t)cT * cB * c2H];  // [T][B][2H]
static __device__ float g_Wt  [2][(size_t)cKW * cNW];   // k-major padded tf32 W_hh
static __device__ float g_Wih [2][(size_t)c3H * cIN];   // tf32 W_ih
static __device__ float g_Wwc [(size_t)c2H * c2H];      // tf32 W_word
static __device__ float g_Wsc [(size_t)c2H * c2H];      // tf32 W_sent
static __device__ float g_scorep[(size_t)cTB * 4];      // word-score partials
static __device__ float g_alpha[(size_t)cB * cT];
static __device__ float g_wv  [(size_t)cB * c2H];
static __device__ float g_u2  [(size_t)cB * c2H];
static __device__ float g_s2  [cB];
static __device__ float g_sent[(size_t)cNB * c2H];

// ---------------------------------------------------------------------------
// Helpers
// ---------------------------------------------------------------------------
__device__ __forceinline__ float to_tf32(float x) {
    float r;
    asm("cvt.rna.tf32.f32 %0, %1;\n" : "=f"(r) : "f"(x));
    return r;
}
__device__ __forceinline__ float sigmoidf(float x) {
    return 1.f / (1.f + expf(-x));
}
__device__ __forceinline__ unsigned int smem_u32(const void* p) {
    return (unsigned int)__cvta_generic_to_shared(p);
}
__device__ __forceinline__ void cp16(unsigned int d, const void* s, int srcsize) {
    asm volatile("cp.async.cg.shared.global [%0], [%1], 16, %2;\n"
                 :: "r"(d), "l"(s), "r"(srcsize));
}
__device__ __forceinline__ void cp16f(unsigned int d, const void* s) {
    asm volatile("cp.async.cg.shared.global [%0], [%1], 16;\n"
                 :: "r"(d), "l"(s));
}
__device__ __forceinline__ void cp_commit() {
    asm volatile("cp.async.commit_group;\n");
}
template <int N>
__device__ __forceinline__ void cp_wait() {
    asm volatile("cp.async.wait_group %0;\n" :: "n"(N));
}
__device__ __forceinline__ void l2_prefetch(const void* p) {
    asm volatile("prefetch.global.L2 [%0];" :: "l"(p));
}

typedef wmma::fragment<wmma::matrix_a, 16, 16, 8, wmma::precision::tf32, wmma::row_major> FragA;
typedef wmma::fragment<wmma::matrix_b, 16, 16, 8, wmma::precision::tf32, wmma::col_major> FragBc;
typedef wmma::fragment<wmma::matrix_b, 16, 16, 8, wmma::precision::tf32, wmma::row_major> FragBr;
typedef wmma::fragment<wmma::accumulator, 16, 16, 8, float> FragC;

template <class F>
__device__ __forceinline__ void cvt_frag(F& f) {
    #pragma unroll
    for (int i = 0; i < f.num_elements; i++) f.x[i] = to_tf32(f.x[i]);
}

// ---------------------------------------------------------------------------
// Prep / utility kernels
// ---------------------------------------------------------------------------
__global__ void zero_out_kernel(float* p, int n) {
    int i = blockIdx.x * blockDim.x + threadIdx.x;
    if (i < n) p[i] = 0.f;
}

// one merged tf32-rounding prep for W_ih f/r, W_word, W_sent
__global__ void prep_all_kernel(const float* __restrict__ Wihf,
                                const float* __restrict__ Wihr,
                                const float* __restrict__ Wword,
                                const float* __restrict__ Wsent) {
    constexpr int n1 = c3H * cIN;        // 248400
    constexpr int n3 = c2H * c2H;        // 211600
    int i = blockIdx.x * blockDim.x + threadIdx.x;
    if (i < n1)                g_Wih[0][i]            = to_tf32(Wihf[i]);
    else if (i < 2 * n1)       g_Wih[1][i - n1]       = to_tf32(Wihr[i - n1]);
    else if (i < 2 * n1 + n3)  g_Wwc[i - 2 * n1]      = to_tf32(Wword[i - 2 * n1]);
    else if (i < 2 * n1 + 2 * n3) g_Wsc[i - 2 * n1 - n3] = to_tf32(Wsent[i - 2 * n1 - n3]);
}

// g_Wt[dir][k][g*240 + j] = tf32(Whh[g*230 + j][k]); zero padding elsewhere.
__global__ void wt_prep_kernel(const float* __restrict__ Whhf,
                               const float* __restrict__ Whhr) {
    int i = blockIdx.x * blockDim.x + threadIdx.x;
    if (i >= 2 * cKW * cNW) return;
    int dir = i / (cKW * cNW);
    int r = i % (cKW * cNW);
    int k = r / cNW, n = r % cNW;
    int g = n / cGP, j = n % cGP;
    const float* W = dir ? Whhr : Whhf;
    float v = 0.f;
    if (j < cH && k < cH) v = to_tf32(W[(size_t)(g * cH + j) * cH + k]);
    g_Wt[dir][(size_t)k * cNW + n] = v;
}

// ---------------------------------------------------------------------------
// Input projection: C[M=262144, N=690] = bag @ W^T + b (TN), row remap.
// CTA tile 128x128, warp tile 32x64, 3-stage cp.async, 1 barrier per k-tile.
// ---------------------------------------------------------------------------
constexpr int IP_SMEM = (3 * 4608 + 3 * 4608) * 4;   // 110592 B

__global__ void __launch_bounds__(256, 2) iproj_kernel(
    const float* __restrict__ bag,
    const float* __restrict__ bf, const float* __restrict__ br)
{
    const int z = blockIdx.z;
    const float* __restrict__ W    = g_Wih[z];
    const float* __restrict__ bias = z ? br : bf;
    float* __restrict__ dst        = z ? g_xg_r : g_xg_f;

    extern __shared__ float sm[];
    float* As = sm;               // [3][128][36]
    float* Bs = sm + 3 * 4608;    // [3][128][36] (n-major rows)
    float* Cs = sm;               // [128][132] (aliases; used post-loop)

    const int n0 = blockIdx.x * 128;
    const int m0 = blockIdx.y * 128;
    const int tid = threadIdx.x;
    const int wid = tid >> 5;
    const int wm = wid & 3;       // 32-row quadrant
    const int wn = wid >> 2;      // 64-col half

    constexpr int KT = (cIN + 31) / 32;   // 12

    FragC acc[2][4];
    #pragma unroll
    for (int i = 0; i < 2; i++)
        #pragma unroll
        for (int j = 0; j < 4; j++) wmma::fill_fragment(acc[i][j], 0.f);

    auto load_stage = [&](int st, int k0) {
        float* A = As + st * 4608;
        float* B = Bs + st * 4608;
        #pragma unroll
        for (int q = 0; q < 4; q++) {
            int idx = q * 256 + tid;
            int r = idx >> 3, c4 = idx & 7;
            int k = k0 + c4 * 4;
            cp16(smem_u32(&A[r * 36 + c4 * 4]),
                 bag + (size_t)(m0 + r) * cIN + min(k, cIN - 4),
                 (k + 4 <= cIN) ? 16 : 0);
        }
        #pragma unroll
        for (int q = 0; q < 4; q++) {
            int idx = q * 256 + tid;
            int n = idx >> 3, c4 = idx & 7;
            int k = k0 + c4 * 4;
            int nn = min(n0 + n, c3H - 1);
            cp16(smem_u32(&B[n * 36 + c4 * 4]),
                 W + (size_t)nn * cIN + min(k, cIN - 4),
                 (n0 + n < c3H && k + 4 <= cIN) ? 16 : 0);
        }
    };

    load_stage(0, 0); cp_commit();
    load_stage(1, 32); cp_commit();

    for (int kt = 0; kt < KT; kt++) {
        if (kt + 1 < KT) cp_wait<1>(); else cp_wait<0>();
        __syncthreads();
        if (kt + 2 < KT) { load_stage((kt + 2) % 3, (kt + 2) * 32); cp_commit(); }

        float* A = As + (kt % 3) * 4608;
        float* B = Bs + (kt % 3) * 4608;
        #pragma unroll
        for (int kk = 0; kk < 32; kk += 8) {
            FragA a0, a1;
            wmma::load_matrix_sync(a0, &A[(wm * 32) * 36 + kk], 36);
            wmma::load_matrix_sync(a1, &A[(wm * 32 + 16) * 36 + kk], 36);
            cvt_frag(a0); cvt_frag(a1);
            #pragma unroll
            for (int j = 0; j < 4; j++) {
                FragBc b;
                wmma::load_matrix_sync(b, &B[(wn * 64 + j * 16) * 36 + kk], 36);
                wmma::mma_sync(acc[0][j], a0, b, acc[0][j]);
                wmma::mma_sync(acc[1][j], a1, b, acc[1][j]);
            }
        }
    }
    __syncthreads();

    #pragma unroll
    for (int i = 0; i < 2; i++)
        #pragma unroll
        for (int j = 0; j < 4; j++)
            wmma::store_matrix_sync(&Cs[(wm * 32 + i * 16) * 132 + wn * 64 + j * 16],
                                    acc[i][j], 132, wmma::mem_row_major);
    __syncthreads();

    #pragma unroll
    for (int q = 0; q < 64; q++) {
        int idx = q * 256 + tid;
        int r = idx >> 7, c = idx & 127;
        int n = n0 + c;
        if (n < c3H) {
            int m = m0 + r;
            size_t crow = (size_t)(m & (cT - 1)) * cB + (m >> 6);
            dst[crow * c3H + n] = Cs[r * 132 + c] + bias[n];
        }
    }
}

// ---------------------------------------------------------------------------
// Attention GEMM (NN). N=K=460, pre-tf32 B. CTA 128x128, warp 32x64.
//  SEL 2: A=g_out, fused epilogue: score partials -> g_scorep (no u stored)
//  SEL 3: A=g_wv,  epilogue: u2 = tanh(...) -> g_u2
// ---------------------------------------------------------------------------
constexpr int AT_SMEM = (3 * 4608 + 3 * 4224) * 4;   // 105984 B

template <int SEL>
__global__ void __launch_bounds__(256, 2) attn_gemm_kernel(
    const float* __restrict__ bias, const float* __restrict__ pj)
{
    const float* __restrict__ A  = (SEL == 2) ? g_out : g_wv;
    const float* __restrict__ Bw = (SEL == 2) ? g_Wwc : g_Wsc;
    constexpr int N = c2H, K = c2H;

    extern __shared__ float sm[];
    float* As = sm;               // [3][128][36]
    float* Bs = sm + 3 * 4608;    // [3][32][132] (k-major rows)
    float* Cs = sm;               // [128][132]

    const int n0 = blockIdx.x * 128;
    const int m0 = blockIdx.y * 128;
    const int tid = threadIdx.x;
    const int wid = tid >> 5;
    const int lane = tid & 31;
    const int wm = wid & 3;
    const int wn = wid >> 2;

    constexpr int KT = (K + 31) / 32;   // 15

    FragC acc[2][4];
    #pragma unroll
    for (int i = 0; i < 2; i++)
        #pragma unroll
        for (int j = 0; j < 4; j++) wmma::fill_fragment(acc[i][j], 0.f);

    auto load_stage = [&](int st, int k0) {
        float* Ab = As + st * 4608;
        float* Bb = Bs + st * 4224;
        #pragma unroll
        for (int q = 0; q < 4; q++) {
            int idx = q * 256 + tid;
            int r = idx >> 3, c4 = idx & 7;
            int k = k0 + c4 * 4;
            cp16(smem_u32(&Ab[r * 36 + c4 * 4]),
                 A + (size_t)(m0 + r) * K + min(k, K - 4),
                 (k + 4 <= K) ? 16 : 0);
        }
        #pragma unroll
        for (int q = 0; q < 4; q++) {
            int idx = q * 256 + tid;
            int k = idx >> 5, n4 = idx & 31;
            int kk = k0 + k;
            int n = n0 + n4 * 4;
            cp16(smem_u32(&Bb[k * 132 + n4 * 4]),
                 Bw + (size_t)min(kk, K - 1) * N + min(n, N - 4),
                 (kk < K && n + 4 <= N) ? 16 : 0);
        }
    };

    load_stage(0, 0); cp_commit();
    load_stage(1, 32); cp_commit();

    for (int kt = 0; kt < KT; kt++) {
        if (kt + 1 < KT) cp_wait<1>(); else cp_wait<0>();
        __syncthreads();
        if (kt + 2 < KT) { load_stage((kt + 2) % 3, (kt + 2) * 32); cp_commit(); }

        float* Ab = As + (kt % 3) * 4608;
        float* Bb = Bs + (kt % 3) * 4224;
        #pragma unroll
        for (int kk = 0; kk < 32; kk += 8) {
            FragA a0, a1;
            wmma::load_matrix_sync(a0, &Ab[(wm * 32) * 36 + kk], 36);
            wmma::load_matrix_sync(a1, &Ab[(wm * 32 + 16) * 36 + kk], 36);
            cvt_frag(a0); cvt_frag(a1);
            #pragma unroll
            for (int j = 0; j < 4; j++) {
                FragBr b;
                wmma::load_matrix_sync(b, &Bb[kk * 132 + wn * 64 + j * 16], 132);
                wmma::mma_sync(acc[0][j], a0, b, acc[0][j]);
                wmma::mma_sync(acc[1][j], a1, b, acc[1][j]);
            }
        }
    }
    __syncthreads();

    #pragma unroll
    for (int i = 0; i < 2; i++)
        #pragma unroll
        for (int j = 0; j < 4; j++)
            wmma::store_matrix_sync(&Cs[(wm * 32 + i * 16) * 132 + wn * 64 + j * 16],
                                    acc[i][j], 132, wmma::mem_row_major);
    __syncthreads();

    if (SEL == 2) {
        // fused: score partial over this n-tile; u never stored.
        #pragma unroll
        for (int rr = 0; rr < 16; rr++) {
            int row = wid * 16 + rr;
            float v = 0.f;
            #pragma unroll
            for (int c4 = 0; c4 < 4; c4++) {
                int n = n0 + lane + c4 * 32;
                if (n < N) v += tanhf(Cs[row * 132 + lane + c4 * 32] + bias[n]) * pj[n];
            }
            #pragma unroll
            for (int o = 16; o; o >>= 1) v += __shfl_xor_sync(0xffffffffu, v, o);
            if (lane == 0)
                g_scorep[(size_t)(m0 + row) * 4 + blockIdx.x] = v;
        }
    } else {
        #pragma unroll
        for (int q = 0; q < 64; q++) {
            int idx = q * 256 + tid;
            int r = idx >> 7, c = idx & 127;
            int n = n0 + c;
            if (n < N)
                g_u2[(size_t)(m0 + r) * N + n] = tanhf(Cs[r * 132 + c] + bias[n]);
        }
    }
}

// ---------------------------------------------------------------------------
// Persistent GRU (R6 v2, best known): one CTA per (64-batch tile, dir).
// W streamed L2 -> smem via double-buffered cp.async in k-chunks of 8.
// smem: hs[64][236] tf32 h, hex[64][236] exact h, Wst[2][8][724], slabs.
// Warp w owns j-tiles {2w, 2w+1} (16 j each) for all 3 gates, all 64 rows.
// ---------------------------------------------------------------------------
constexpr int GRU_HS    = BT * cHS;              // 15104 floats
constexpr int GRU_WST1  = 8 * cWS;               // 5792 floats (one stage)
constexpr int GRU_SLAB  = 16 * 52;               // 832 floats per warp
constexpr int GRU_SMEMF = 2 * GRU_HS + 2 * GRU_WST1 + 8 * GRU_SLAB;  // 48448
constexpr int GRU_SMEM  = GRU_SMEMF * 4;         // 193792 bytes

__global__ void __launch_bounds__(256, 1) gru_persistent_kernel(
    const float* __restrict__ bhh_f, const float* __restrict__ bhh_r)
{
    const int dir = blockIdx.y;
    const int b0 = blockIdx.x * BT;
    const float* __restrict__ xg  = dir ? g_xg_r : g_xg_f;
    const float* __restrict__ bhh = dir ? bhh_r : bhh_f;
    const float* __restrict__ Wd  = g_Wt[dir];

    extern __shared__ float sm[];
    float* hs   = sm;                        // [64][236]
    float* hex  = sm + GRU_HS;               // [64][236]
    float* Wst  = sm + 2 * GRU_HS;           // [2][8][724]
    const int tid = threadIdx.x;
    const int wid = tid >> 5;
    const int lane = tid & 31;
    float* slab = sm + 2 * GRU_HS + 2 * GRU_WST1 + wid * GRU_SLAB;

    for (int i = tid; i < 2 * GRU_HS; i += 256) sm[i] = 0.f;

    // stage W rows [k0, k0+8) into buffer buf (1440 cp16 ops)
    auto stage = [&](int buf, int k0) {
        const float* src = Wd + (size_t)k0 * cNW;
        float* dstW = Wst + buf * GRU_WST1;
        #pragma unroll
        for (int q = 0; q < 6; q++) {
            int idx = q * 256 + tid;
            if (idx < 1440) {
                int r = idx / 180, c = idx % 180;
                cp16f(smem_u32(&dstW[r * cWS + c * 4]), src + r * cNW + c * 4);
            }
        }
    };

    stage(0, 0);
    cp_commit();
    __syncthreads();   // also covers hs/hex zero-init

    int gbuf = 0;
    FragC acc[2][3][4];

    for (int s = 0; s < cT; s++) {
        const int t = dir ? (cT - 1 - s) : s;

        // L2-prefetch this step's xg rows
        {
            const float* base = xg + ((size_t)t * cB + b0) * c3H;
            #pragma unroll
            for (int q = 0; q < 6; q++) {
                int line = q * 256 + tid;
                if (line < 1408) {
                    int r = line / 22, c = line % 22;
                    int off = c * 32;
                    if (off < c3H) l2_prefetch(base + (size_t)r * c3H + off);
                }
            }
        }

        #pragma unroll
        for (int p = 0; p < 2; p++)
            #pragma unroll
            for (int g = 0; g < 3; g++)
                #pragma unroll
                for (int m = 0; m < 4; m++) wmma::fill_fragment(acc[p][g][m], 0.f);

        for (int c = 0; c < 29; c++) {
            const bool last = (s == cT - 1) && (c == 28);
            if (!last) {
                stage(gbuf ^ 1, (c == 28) ? 0 : (c + 1) * 8);
                cp_commit();
                cp_wait<1>();
            } else {
                cp_wait<0>();
            }
            __syncthreads();

            float* Wb = Wst + gbuf * GRU_WST1;
            const int k0 = c * 8;
            #pragma unroll
            for (int p = 0; p < 2; p++) {
                const int jt = wid * 2 + p;
                if (jt < 15) {
                    FragBr bf[3];
                    #pragma unroll
                    for (int g = 0; g < 3; g++)
                        wmma::load_matrix_sync(bf[g], Wb + g * cGP + jt * 16, cWS);
                    #pragma unroll
                    for (int m = 0; m < 4; m++) {
                        FragA af;
                        wmma::load_matrix_sync(af, hs + (m * 16) * cHS + k0, cHS);
                        #pragma unroll
                        for (int g = 0; g < 3; g++)
                            wmma::mma_sync(acc[p][g][m], af, bf[g], acc[p][g][m]);
                    }
                }
            }
            gbuf ^= 1;
            __syncthreads();   // chunk consumed; next staging may overwrite
        }

        // all mma done -> safe to overwrite hs
        #pragma unroll
        for (int p = 0; p < 2; p++) {
            const int jt = wid * 2 + p;
            if (jt >= 15) continue;
            #pragma unroll
            for (int m = 0; m < 4; m++) {
                wmma::store_matrix_sync(slab +  0, acc[p][0][m], 52, wmma::mem_row_major);
                wmma::store_matrix_sync(slab + 16, acc[p][1][m], 52, wmma::mem_row_major);
                wmma::store_matrix_sync(slab + 32, acc[p][2][m], 52, wmma::mem_row_major);
                __syncwarp();
                #pragma unroll
                for (int e = 0; e < 8; e++) {
                    int idx = e * 32 + lane;
                    int rr = idx >> 4, cc = idx & 15;
                    int j = jt * 16 + cc;
                    if (j < cH) {
                        int bl = m * 16 + rr;
                        int b = b0 + bl;
                        const float* xrow = xg + ((size_t)t * cB + b) * c3H;
                        float hgr = slab[rr * 52 + cc];
                        float hgz = slab[rr * 52 + 16 + cc];
                        float hgn = slab[rr * 52 + 32 + cc];
                        float r = sigmoidf(xrow[j]          + hgr + bhh[j]);
                        float z = sigmoidf(xrow[cH + j]     + hgz + bhh[cH + j]);
                        float n = tanhf(xrow[2 * cH + j] + r * (hgn + bhh[2 * cH + j]));
                        float hold = hex[bl * cHS + j];
                        float h2 = (1.f - z) * n + z * hold;
                        hex[bl * cHS + j] = h2;
                        hs[bl * cHS + j] = to_tf32(h2);
                        g_out[((size_t)t * cB + b) * c2H + dir * cH + j] = h2;
                    }
                }
                __syncwarp();
            }
        }
        __syncthreads();   // hs(t+1) ready before next step's mma reads it
    }
}

// ---------------------------------------------------------------------------
// small kernels
// ---------------------------------------------------------------------------
__global__ void rowdot_sent_kernel(const float* __restrict__ proj) {
    int row = blockIdx.x * 8 + (threadIdx.x >> 5);
    if (row >= cB) return;
    int lane = threadIdx.x & 31;
    const float* u = g_u2 + (size_t)row * c2H;
    float s = 0.f;
    for (int j = lane; j < c2H; j += 32) s += u[j] * proj[j];
    #pragma unroll
    for (int o = 16; o; o >>= 1) s += __shfl_xor_sync(0xffffffffu, s, o);
    if (lane == 0) g_s2[row] = s;
}

// softmax over T per batch element (warp per b); sums 4 score partials per (t,b)
__global__ void softmaxT_kernel() {
    int b = blockIdx.x * 8 + (threadIdx.x >> 5);
    int lane = threadIdx.x & 31;
    const float* p0 = g_scorep + ((size_t)lane * cB + b) * 4;
    const float* p1 = g_scorep + ((size_t)(lane + 32) * cB + b) * 4;
    float v0 = 0.f, v1 = 0.f;
    #pragma unroll
    for (int i = 0; i < 4; i++) { v0 += p0[i]; v1 += p1[i]; }
    float m = fmaxf(v0, v1);
    #pragma unroll
    for (int o = 16; o; o >>= 1) m = fmaxf(m, __shfl_xor_sync(0xffffffffu, m, o));
    float e0 = expf(v0 - m), e1 = expf(v1 - m);
    float sum = e0 + e1;
    #pragma unroll
    for (int o = 16; o; o >>= 1) sum += __shfl_xor_sync(0xffffffffu, sum, o);
    float inv = 1.f / sum;
    g_alpha[(size_t)b * cT + lane] = e0 * inv;
    g_alpha[(size_t)b * cT + lane + 32] = e1 * inv;
}

__global__ void wordvec_kernel() {
    int b = blockIdx.y;
    int h = blockIdx.x * 128 + threadIdx.x;
    if (h >= c2H) return;
    const float* al = g_alpha + (size_t)b * cT;
    float s = 0.f;
    for (int t = 0; t < cT; t++)
        s += al[t] * g_out[((size_t)t * cB + b) * c2H + h];
    g_wv[(size_t)b * c2H + h] = s;
}

__global__ void sentvec_kernel() {
    int nb = blockIdx.x;
    __shared__ float beta[cMS];
    if (threadIdx.x == 0) {
        float v[cMS];
        float m = -1e30f;
        for (int ms = 0; ms < cMS; ms++) { v[ms] = g_s2[nb * cMS + ms]; m = fmaxf(m, v[ms]); }
        float sum = 0.f;
        for (int ms = 0; ms < cMS; ms++) { v[ms] = expf(v[ms] - m); sum += v[ms]; }
        float inv = 1.f / sum;
        for (int ms = 0; ms < cMS; ms++) beta[ms] = v[ms] * inv;
    }
    __syncthreads();
    for (int h = threadIdx.x; h < c2H; h += blockDim.x) {
        float s = 0.f;
        #pragma unroll
        for (int ms = 0; ms < cMS; ms++)
            s += beta[ms] * g_wv[((size_t)nb * cMS + ms) * c2H + h];
        g_sent[(size_t)nb * c2H + h] = s;
    }
}

__global__ void fc_scatter_kernel(const float* __restrict__ fcW,
                                  const float* __restrict__ fcb,
                                  const int* __restrict__ pairs,
                                  float* __restrict__ out)
{
    int nb = blockIdx.x;
    __shared__ float sv[c2H];
    for (int k = threadIdx.x; k < c2H; k += blockDim.x)
        sv[k] = g_sent[(size_t)nb * c2H + k];
    __syncthreads();
    int o = threadIdx.x;
    if (o < cOUT) {
        const float* w = fcW + (size_t)o * c2H;
        float s = fcb[o];
        for (int k = 0; k < c2H; k++) s += sv[k] * w[k];
        int d  = pairs[nb * 3 + 0];
        int e1 = pairs[nb * 3 + 1];
        int e2 = pairs[nb * 3 + 2];
        out[(((size_t)d * cENT + e1) * cENT + e2) * cOUT + o] = s;
    }
}

// ---------------------------------------------------------------------------
extern "C" void kernel_launch(void* const* d_in, const int* in_sizes, int n_in,
                              void* d_out, int out_size) {
    const float* bag   = (const float*)d_in[0];
    const float* Wihf  = (const float*)d_in[1];
    const float* Whhf  = (const float*)d_in[2];
    const float* bihf  = (const float*)d_in[3];
    const float* bhhf  = (const float*)d_in[4];
    const float* Wihr  = (const float*)d_in[5];
    const float* Whhr  = (const float*)d_in[6];
    const float* bihr  = (const float*)d_in[7];
    const float* bhhr  = (const float*)d_in[8];
    const float* Wword = (const float*)d_in[9];
    const float* bword = (const float*)d_in[10];
    const float* pjw   = (const float*)d_in[11];
    const float* Wsent = (const float*)d_in[12];
    const float* bsent = (const float*)d_in[13];
    const float* pjs   = (const float*)d_in[14];
    const float* fcW   = (const float*)d_in[15];
    const float* fcb   = (const float*)d_in[16];
    const int*   pairs = (const int*)d_in[17];
    float* out = (float*)d_out;

    static int attr_done = 0;
    if (!attr_done) {
        cudaFuncSetAttribute(iproj_kernel, cudaFuncAttributeMaxDynamicSharedMemorySize, IP_SMEM);
        cudaFuncSetAttribute(attn_gemm_kernel<2>, cudaFuncAttributeMaxDynamicSharedMemorySize, AT_SMEM);
        cudaFuncSetAttribute(attn_gemm_kernel<3>, cudaFuncAttributeMaxDynamicSharedMemorySize, AT_SMEM);
        cudaFuncSetAttribute(gru_persistent_kernel, cudaFuncAttributeMaxDynamicSharedMemorySize, GRU_SMEM);
        attr_done = 1;
    }

    constexpr int prep_n = 2 * c3H * cIN + 2 * c2H * c2H;

    zero_out_kernel<<<(out_size + 255) / 256, 256>>>(out, out_size);
    wt_prep_kernel<<<(2 * cKW * cNW + 255) / 256, 256>>>(Whhf, Whhr);
    prep_all_kernel<<<(prep_n + 255) / 256, 256>>>(Wihf, Wihr, Wword, Wsent);

    // input projections (both dirs)
    {
        dim3 grid((c3H + 127) / 128, (int)(cTB / 128), 2);
        iproj_kernel<<<grid, 256, IP_SMEM>>>(bag, bihf, bihr);
    }

    // GRU recurrence: single persistent launch, 128 CTAs = one wave
    {
        dim3 grid(cB / BT, 2);
        gru_persistent_kernel<<<grid, 256, GRU_SMEM>>>(bhhf, bhhr);
    }

    // word attention (scores fused; no u materialized)
    {
        dim3 grid((c2H + 127) / 128, (int)(cTB / 128));
        attn_gemm_kernel<2><<<grid, 256, AT_SMEM>>>(bword, pjw);
    }
    softmaxT_kernel<<<cB / 8, 256>>>();
    {
        dim3 grid((c2H + 127) / 128, cB);
        wordvec_kernel<<<grid, 128>>>();
    }

    // sentence attention
    {
        dim3 grid((c2H + 127) / 128, cB / 128);
        attn_gemm_kernel<3><<<grid, 256, AT_SMEM>>>(bsent, nullptr);
    }
    rowdot_sent_kernel<<<cB / 8, 256>>>(pjs);
    sentvec_kernel<<<cNB, 128>>>();

    fc_scatter_kernel<<<cNB, 64>>>(fcW, fcb, pairs, out);
}

// round 13
// speedup vs baseline: 1.1730x; 1.0579x over previous
#include <cuda_runtime.h>
#include <mma.h>
#include <math.h>
#include <cstdint>

using namespace nvcuda;

// Problem constants
constexpr int cNB   = 512;
constexpr int cMS   = 8;
constexpr int cT    = 64;
constexpr int cIN   = 360;
constexpr int cH    = 230;
constexpr int cOUT  = 53;
constexpr int cENT  = 8;
constexpr int cB    = cNB * cMS;     // 4096
constexpr int c3H   = 3 * cH;        // 690
constexpr int c2H   = 2 * cH;        // 460
constexpr size_t cTB = (size_t)cT * cB;   // 262144

constexpr int cGP   = 240;           // per-gate padded width in g_Wt
constexpr int BT    = 64;            // batch tile per GRU CTA
constexpr int cHS   = 236;           // hs/hex smem row stride
constexpr int cWS   = 724;           // GRU W row stride (720 data + 4 pad)
constexpr int NCHK  = 29;            // GRU k-chunks of 8 (29*8 = 232 >= 230)

// ---------------------------------------------------------------------------
// Scratch
// ---------------------------------------------------------------------------
static __device__ float g_xg_f[(size_t)cT * cB * c3H];  // [T][B][3H]
static __device__ float g_xg_r[(size_t)cT * cB * c3H];
static __device__ float g_out [(size_t)cT * cB * c2H];  // [T][B][2H]
// chunk-contiguous tf32 W_hh: [dir][29 chunks][8 k][724 n]
static __device__ float g_Wt  [2][(size_t)NCHK * 8 * cWS];
// tiled tf32 W_ih: [z][6 ntile][12 ktile][128 n][36 k]
static __device__ float g_Wih2[2][(size_t)6 * 12 * 128 * 36];
// tiled tf32 W_word/W_sent: [sel][4 ntile][15 ktile][32 k][132 n]
static __device__ float g_Wat [2][(size_t)4 * 15 * 32 * 132];
static __device__ float g_scorep[(size_t)cTB * 4];      // word-score partials
static __device__ float g_alpha[(size_t)cB * cT];
static __device__ float g_wv  [(size_t)cB * c2H];
static __device__ float g_u2  [(size_t)cB * c2H];
static __device__ float g_s2  [cB];
static __device__ float g_sent[(size_t)cNB * c2H];

// ---------------------------------------------------------------------------
// Helpers
// ---------------------------------------------------------------------------
__device__ __forceinline__ float to_tf32(float x) {
    float r;
    asm("cvt.rna.tf32.f32 %0, %1;\n" : "=f"(r) : "f"(x));
    return r;
}
__device__ __forceinline__ float sigmoidf(float x) {
    return 1.f / (1.f + expf(-x));
}
__device__ __forceinline__ unsigned int smem_u32(const void* p) {
    return (unsigned int)__cvta_generic_to_shared(p);
}
__device__ __forceinline__ void cp16(unsigned int d, const void* s, int srcsize) {
    asm volatile("cp.async.cg.shared.global [%0], [%1], 16, %2;\n"
                 :: "r"(d), "l"(s), "r"(srcsize));
}
__device__ __forceinline__ void cp_commit() {
    asm volatile("cp.async.commit_group;\n");
}
template <int N>
__device__ __forceinline__ void cp_wait() {
    asm volatile("cp.async.wait_group %0;\n" :: "n"(N));
}
__device__ __forceinline__ void l2_prefetch(const void* p) {
    asm volatile("prefetch.global.L2 [%0];" :: "l"(p));
}
// ---- mbarrier + bulk copy ----
__device__ __forceinline__ void mbar_init(unsigned mbar, unsigned count) {
    asm volatile("mbarrier.init.shared.b64 [%0], %1;" :: "r"(mbar), "r"(count) : "memory");
}
__device__ __forceinline__ void mbar_expect(unsigned mbar, unsigned bytes) {
    asm volatile("mbarrier.arrive.expect_tx.shared.b64 _, [%0], %1;"
                 :: "r"(mbar), "r"(bytes) : "memory");
}
__device__ __forceinline__ void mbar_wait(unsigned mbar, int parity) {
    asm volatile(
        "{\n\t.reg .pred P;\n\t"
        "WL_%=:\n\t"
        "mbarrier.try_wait.parity.acquire.cta.shared::cta.b64 P, [%0], %1, 0x989680;\n\t"
        "@P bra.uni WD_%=;\n\t"
        "bra.uni WL_%=;\n\t"
        "WD_%=:\n\t}"
        :: "r"(mbar), "r"(parity) : "memory");
}
__device__ __forceinline__ void cp_bulk(unsigned dst, const void* src,
                                        unsigned bytes, unsigned mbar) {
    asm volatile(
        "cp.async.bulk.shared::cta.global.mbarrier::complete_tx::bytes [%0], [%1], %2, [%3];\n"
        :: "r"(dst), "l"(src), "r"(bytes), "r"(mbar) : "memory");
}

typedef wmma::fragment<wmma::matrix_a, 16, 16, 8, wmma::precision::tf32, wmma::row_major> FragA;
typedef wmma::fragment<wmma::matrix_b, 16, 16, 8, wmma::precision::tf32, wmma::col_major> FragBc;
typedef wmma::fragment<wmma::matrix_b, 16, 16, 8, wmma::precision::tf32, wmma::row_major> FragBr;
typedef wmma::fragment<wmma::accumulator, 16, 16, 8, float> FragC;

template <class F>
__device__ __forceinline__ void cvt_frag(F& f) {
    #pragma unroll
    for (int i = 0; i < f.num_elements; i++) f.x[i] = to_tf32(f.x[i]);
}

// ---------------------------------------------------------------------------
// Prep / utility kernels
// ---------------------------------------------------------------------------
__global__ void zero_out_kernel(float* p, int n) {
    int i = blockIdx.x * blockDim.x + threadIdx.x;
    if (i < n) p[i] = 0.f;
}

// g_Wt[dir][cc][k][n]: n<720 -> g=n/240, j=n%240; value tf32(Whh[g*230+j][K]),
// K = cc*8+k; zero for j>=230, K>=230, n>=720.
__global__ void wt_prep_kernel(const float* __restrict__ Whhf,
                               const float* __restrict__ Whhr) {
    constexpr int PER = NCHK * 8 * cWS;
    int i = blockIdx.x * blockDim.x + threadIdx.x;
    if (i >= 2 * PER) return;
    int dir = i / PER;
    int r = i % PER;
    int cc = r / (8 * cWS);
    int r2 = r % (8 * cWS);
    int k = r2 / cWS, n = r2 % cWS;
    int K = cc * 8 + k;
    float v = 0.f;
    if (n < 720) {
        int g = n / cGP, j = n % cGP;
        const float* W = dir ? Whhr : Whhf;
        if (j < cH && K < cH) v = to_tf32(W[(size_t)(g * cH + j) * cH + K]);
    }
    g_Wt[dir][(size_t)r] = v;
}

// g_Wih2[z][bx][kt][n][kk]: value tf32(Wih[bx*128+n][kt*32+kk]) (kk<32), else 0
__global__ void wih2_prep_kernel(const float* __restrict__ Wf,
                                 const float* __restrict__ Wr) {
    constexpr int PER = 6 * 12 * 128 * 36;
    int i = blockIdx.x * blockDim.x + threadIdx.x;
    if (i >= 2 * PER) return;
    int z = i / PER;
    int r = i % PER;
    int bx = r / (12 * 128 * 36);
    int r2 = r % (12 * 128 * 36);
    int kt = r2 / (128 * 36);
    int r3 = r2 % (128 * 36);
    int n = r3 / 36, kk = r3 % 36;
    int N = bx * 128 + n, K = kt * 32 + kk;
    const float* W = z ? Wr : Wf;
    float v = 0.f;
    if (kk < 32 && N < c3H && K < cIN) v = to_tf32(W[(size_t)N * cIN + K]);
    g_Wih2[z][(size_t)r] = v;
}

// g_Wat[sel][bx][kt][k][nn]: value tf32(W[kt*32+k][bx*128+nn]) for nn<128, else 0
__global__ void wat_prep_kernel(const float* __restrict__ Wword,
                                const float* __restrict__ Wsent) {
    constexpr int PER = 4 * 15 * 32 * 132;
    int i = blockIdx.x * blockDim.x + threadIdx.x;
    if (i >= 2 * PER) return;
    int sel = i / PER;
    int r = i % PER;
    int bx = r / (15 * 32 * 132);
    int r2 = r % (15 * 32 * 132);
    int kt = r2 / (32 * 132);
    int r3 = r2 % (32 * 132);
    int k = r3 / 132, nn = r3 % 132;
    int N = bx * 128 + nn, K = kt * 32 + k;
    const float* W = sel ? Wsent : Wword;
    float v = 0.f;
    if (nn < 128 && N < c2H && K < c2H) v = to_tf32(W[(size_t)K * c2H + N]);
    g_Wat[sel][(size_t)r] = v;
}

// ---------------------------------------------------------------------------
// Input projection: C[M=262144, N=690] = bag @ W^T + b (TN), row remap.
// CTA 128x128, warp 32x64. A: 3-stage cp16 groups. B: 3-stage bulk+mbarrier.
// ---------------------------------------------------------------------------
constexpr int IP_SMEMF = 3 * 4608 + 3 * 4608 + 8;    // + mbar area
constexpr int IP_SMEM  = IP_SMEMF * 4;               // 110624 B

__global__ void __launch_bounds__(256, 2) iproj_kernel(
    const float* __restrict__ bag,
    const float* __restrict__ bf, const float* __restrict__ br)
{
    const int z = blockIdx.z;
    const float* __restrict__ bias = z ? br : bf;
    float* __restrict__ dst        = z ? g_xg_r : g_xg_f;

    extern __shared__ float sm[];
    float* As = sm;               // [3][128][36]
    float* Bs = sm + 3 * 4608;    // [3][128][36]
    float* Cs = sm;               // [128][132] (aliases; post-loop only)
    const unsigned mb = smem_u32(sm + 6 * 4608);

    const int bx = blockIdx.x;
    const int n0 = bx * 128;
    const int m0 = blockIdx.y * 128;
    const int tid = threadIdx.x;
    const int wid = tid >> 5;
    const int wm = wid & 3;
    const int wn = wid >> 2;

    constexpr int KT = (cIN + 31) / 32;   // 12
    const float* Wsrc = g_Wih2[z] + (size_t)bx * 12 * 4608;

    if (tid < 3) mbar_init(mb + tid * 8, 1);

    FragC acc[2][4];
    #pragma unroll
    for (int i = 0; i < 2; i++)
        #pragma unroll
        for (int j = 0; j < 4; j++) wmma::fill_fragment(acc[i][j], 0.f);

    auto stageA = [&](int kt) {
        float* A = As + (kt % 3) * 4608;
        int k0 = kt * 32;
        #pragma unroll
        for (int q = 0; q < 4; q++) {
            int idx = q * 256 + tid;
            int r = idx >> 3, c4 = idx & 7;
            int k = k0 + c4 * 4;
            cp16(smem_u32(&A[r * 36 + c4 * 4]),
                 bag + (size_t)(m0 + r) * cIN + min(k, cIN - 4),
                 (k + 4 <= cIN) ? 16 : 0);
        }
    };
    auto issueB = [&](int kt) {
        if (tid == 0) {
            int buf = kt % 3;
            mbar_expect(mb + buf * 8, 18432);
            cp_bulk(smem_u32(Bs) + buf * 18432, Wsrc + (size_t)kt * 4608,
                    18432, mb + buf * 8);
        }
    };

    stageA(0); cp_commit();
    stageA(1); cp_commit();
    __syncthreads();              // mbar init visible
    issueB(0); issueB(1);

    for (int kt = 0; kt < KT; kt++) {
        if (kt + 1 < KT) cp_wait<1>(); else cp_wait<0>();
        mbar_wait(mb + (kt % 3) * 8, (kt / 3) & 1);
        __syncthreads();
        if (kt + 2 < KT) { stageA(kt + 2); cp_commit(); issueB(kt + 2); }

        float* A = As + (kt % 3) * 4608;
        float* B = Bs + (kt % 3) * 4608;
        #pragma unroll
        for (int kk = 0; kk < 32; kk += 8) {
            FragA a0, a1;
            wmma::load_matrix_sync(a0, &A[(wm * 32) * 36 + kk], 36);
            wmma::load_matrix_sync(a1, &A[(wm * 32 + 16) * 36 + kk], 36);
            cvt_frag(a0); cvt_frag(a1);
            #pragma unroll
            for (int j = 0; j < 4; j++) {
                FragBc b;
                wmma::load_matrix_sync(b, &B[(wn * 64 + j * 16) * 36 + kk], 36);
                wmma::mma_sync(acc[0][j], a0, b, acc[0][j]);
                wmma::mma_sync(acc[1][j], a1, b, acc[1][j]);
            }
        }
    }
    __syncthreads();

    #pragma unroll
    for (int i = 0; i < 2; i++)
        #pragma unroll
        for (int j = 0; j < 4; j++)
            wmma::store_matrix_sync(&Cs[(wm * 32 + i * 16) * 132 + wn * 64 + j * 16],
                                    acc[i][j], 132, wmma::mem_row_major);
    __syncthreads();

    #pragma unroll
    for (int q = 0; q < 64; q++) {
        int idx = q * 256 + tid;
        int r = idx >> 7, c = idx & 127;
        int n = n0 + c;
        if (n < c3H) {
            int m = m0 + r;
            size_t crow = (size_t)(m & (cT - 1)) * cB + (m >> 6);
            dst[crow * c3H + n] = Cs[r * 132 + c] + bias[n];
        }
    }
}

// ---------------------------------------------------------------------------
// Attention GEMM (NN). N=K=460. CTA 128x128, warp 32x64.
// A: cp16 groups. B: 3-stage bulk+mbarrier from tiled g_Wat.
//  SEL 2: A=g_out, fused epilogue -> g_scorep.  SEL 3: A=g_wv -> g_u2.
// ---------------------------------------------------------------------------
constexpr int AT_SMEMF = 3 * 4608 + 3 * 4224 + 8;
constexpr int AT_SMEM  = AT_SMEMF * 4;               // 106016 B

template <int SEL>
__global__ void __launch_bounds__(256, 2) attn_gemm_kernel(
    const float* __restrict__ bias, const float* __restrict__ pj)
{
    const float* __restrict__ A  = (SEL == 2) ? g_out : g_wv;
    constexpr int N = c2H, K = c2H;

    extern __shared__ float sm[];
    float* As = sm;               // [3][128][36]
    float* Bs = sm + 3 * 4608;    // [3][32][132]
    float* Cs = sm;               // [128][132]
    const unsigned mb = smem_u32(sm + 3 * 4608 + 3 * 4224);

    const int bx = blockIdx.x;
    const int n0 = bx * 128;
    const int m0 = blockIdx.y * 128;
    const int tid = threadIdx.x;
    const int wid = tid >> 5;
    const int lane = tid & 31;
    const int wm = wid & 3;
    const int wn = wid >> 2;

    constexpr int KT = (K + 31) / 32;   // 15
    const float* Wsrc = g_Wat[(SEL == 2) ? 0 : 1] + (size_t)bx * 15 * 4224;

    if (tid < 3) mbar_init(mb + tid * 8, 1);

    FragC acc[2][4];
    #pragma unroll
    for (int i = 0; i < 2; i++)
        #pragma unroll
        for (int j = 0; j < 4; j++) wmma::fill_fragment(acc[i][j], 0.f);

    auto stageA = [&](int kt) {
        float* Ab = As + (kt % 3) * 4608;
        int k0 = kt * 32;
        #pragma unroll
        for (int q = 0; q < 4; q++) {
            int idx = q * 256 + tid;
            int r = idx >> 3, c4 = idx & 7;
            int k = k0 + c4 * 4;
            cp16(smem_u32(&Ab[r * 36 + c4 * 4]),
                 A + (size_t)(m0 + r) * K + min(k, K - 4),
                 (k + 4 <= K) ? 16 : 0);
        }
    };
    auto issueB = [&](int kt) {
        if (tid == 0) {
            int buf = kt % 3;
            mbar_expect(mb + buf * 8, 16896);
            cp_bulk(smem_u32(Bs) + buf * 16896, Wsrc + (size_t)kt * 4224,
                    16896, mb + buf * 8);
        }
    };

    stageA(0); cp_commit();
    stageA(1); cp_commit();
    __syncthreads();
    issueB(0); issueB(1);

    for (int kt = 0; kt < KT; kt++) {
        if (kt + 1 < KT) cp_wait<1>(); else cp_wait<0>();
        mbar_wait(mb + (kt % 3) * 8, (kt / 3) & 1);
        __syncthreads();
        if (kt + 2 < KT) { stageA(kt + 2); cp_commit(); issueB(kt + 2); }

        float* Ab = As + (kt % 3) * 4608;
        float* Bb = Bs + (kt % 3) * 4224;
        #pragma unroll
        for (int kk = 0; kk < 32; kk += 8) {
            FragA a0, a1;
            wmma::load_matrix_sync(a0, &Ab[(wm * 32) * 36 + kk], 36);
            wmma::load_matrix_sync(a1, &Ab[(wm * 32 + 16) * 36 + kk], 36);
            cvt_frag(a0); cvt_frag(a1);
            #pragma unroll
            for (int j = 0; j < 4; j++) {
                FragBr b;
                wmma::load_matrix_sync(b, &Bb[kk * 132 + wn * 64 + j * 16], 132);
                wmma::mma_sync(acc[0][j], a0, b, acc[0][j]);
                wmma::mma_sync(acc[1][j], a1, b, acc[1][j]);
            }
        }
    }
    __syncthreads();

    #pragma unroll
    for (int i = 0; i < 2; i++)
        #pragma unroll
        for (int j = 0; j < 4; j++)
            wmma::store_matrix_sync(&Cs[(wm * 32 + i * 16) * 132 + wn * 64 + j * 16],
                                    acc[i][j], 132, wmma::mem_row_major);
    __syncthreads();

    if (SEL == 2) {
        #pragma unroll
        for (int rr = 0; rr < 16; rr++) {
            int row = wid * 16 + rr;
            float v = 0.f;
            #pragma unroll
            for (int c4 = 0; c4 < 4; c4++) {
                int n = n0 + lane + c4 * 32;
                if (n < N) v += tanhf(Cs[row * 132 + lane + c4 * 32] + bias[n]) * pj[n];
            }
            #pragma unroll
            for (int o = 16; o; o >>= 1) v += __shfl_xor_sync(0xffffffffu, v, o);
            if (lane == 0)
                g_scorep[(size_t)(m0 + row) * 4 + bx] = v;
        }
    } else {
        #pragma unroll
        for (int q = 0; q < 64; q++) {
            int idx = q * 256 + tid;
            int r = idx >> 7, c = idx & 127;
            int n = n0 + c;
            if (n < N)
                g_u2[(size_t)(m0 + r) * N + n] = tanhf(Cs[r * 132 + c] + bias[n]);
        }
    }
}

// ---------------------------------------------------------------------------
// Persistent GRU v5: R6-v2 compute structure, W staging via cp.async.bulk.
// One CTA per (64-batch tile, dir), 128 CTAs = one wave. 3 W buffers with
// mbarriers; ONE __syncthreads per chunk. Global chunk counter g pipelines
// the staging across chunks AND steps (W is step-invariant).
// ---------------------------------------------------------------------------
constexpr int GRU_HS    = BT * cHS;              // 15104 floats
constexpr int GRU_WST1  = 8 * cWS;               // 5792 floats per buffer
constexpr int GRU_WB    = GRU_WST1 * 4;          // 23168 bytes
constexpr int GRU_SLAB  = 16 * 52;               // 832 floats per warp
constexpr int GRU_SMEMF = 2 * GRU_HS + 3 * GRU_WST1 + 8 * GRU_SLAB + 8;
constexpr int GRU_SMEM  = GRU_SMEMF * 4;         // 217024 bytes

__global__ void __launch_bounds__(256, 1) gru_persistent_kernel(
    const float* __restrict__ bhh_f, const float* __restrict__ bhh_r)
{
    const int dir = blockIdx.y;
    const int b0 = blockIdx.x * BT;
    const float* __restrict__ xg  = dir ? g_xg_r : g_xg_f;
    const float* __restrict__ bhh = dir ? bhh_r : bhh_f;
    const float* __restrict__ Wd  = g_Wt[dir];

    extern __shared__ float sm[];
    float* hs   = sm;                        // [64][236]
    float* hex  = sm + GRU_HS;               // [64][236]
    float* Wst  = sm + 2 * GRU_HS;           // [3][8][724]
    const int tid = threadIdx.x;
    const int wid = tid >> 5;
    const int lane = tid & 31;
    float* slab = sm + 2 * GRU_HS + 3 * GRU_WST1 + wid * GRU_SLAB;
    const unsigned mb = smem_u32(sm + 2 * GRU_HS + 3 * GRU_WST1 + 8 * GRU_SLAB);

    if (tid < 3) mbar_init(mb + tid * 8, 1);
    for (int i = tid; i < 2 * GRU_HS; i += 256) sm[i] = 0.f;
    __syncthreads();

    auto issueW = [&](int gg) {
        if (gg < cT * NCHK && tid == 0) {
            int cc = gg % NCHK;
            int buf = gg % 3;
            mbar_expect(mb + buf * 8, GRU_WB);
            cp_bulk(smem_u32(Wst) + buf * GRU_WB, Wd + (size_t)cc * GRU_WST1,
                    GRU_WB, mb + buf * 8);
        }
    };
    issueW(0); issueW(1);

    int g = 0;
    FragC acc[2][3][4];

    for (int s = 0; s < cT; s++) {
        const int t = dir ? (cT - 1 - s) : s;

        // L2-prefetch this step's xg rows
        {
            const float* base = xg + ((size_t)t * cB + b0) * c3H;
            #pragma unroll
            for (int q = 0; q < 6; q++) {
                int line = q * 256 + tid;
                if (line < 1408) {
                    int r = line / 22, c = line % 22;
                    int off = c * 32;
                    if (off < c3H) l2_prefetch(base + (size_t)r * c3H + off);
                }
            }
        }

        #pragma unroll
        for (int p = 0; p < 2; p++)
            #pragma unroll
            for (int gg = 0; gg < 3; gg++)
                #pragma unroll
                for (int m = 0; m < 4; m++) wmma::fill_fragment(acc[p][gg][m], 0.f);

        for (int c = 0; c < NCHK; c++) {
            const int buf = g % 3;
            mbar_wait(mb + buf * 8, (g / 3) & 1);

            float* Wb = Wst + buf * GRU_WST1;
            const int k0 = c * 8;
            #pragma unroll
            for (int p = 0; p < 2; p++) {
                const int jt = wid * 2 + p;
                if (jt < 15) {
                    FragBr bf[3];
                    #pragma unroll
                    for (int gg = 0; gg < 3; gg++)
                        wmma::load_matrix_sync(bf[gg], Wb + gg * cGP + jt * 16, cWS);
                    #pragma unroll
                    for (int m = 0; m < 4; m++) {
                        FragA af;
                        wmma::load_matrix_sync(af, hs + (m * 16) * cHS + k0, cHS);
                        #pragma unroll
                        for (int gg = 0; gg < 3; gg++)
                            wmma::mma_sync(acc[p][gg][m], af, bf[gg], acc[p][gg][m]);
                    }
                }
            }
            __syncthreads();   // all warps done with buf -> safe to reissue
            issueW(g + 2);
            g++;
        }

        // epilogue: gates + h update (hs safe: all mma done before last barrier)
        #pragma unroll
        for (int p = 0; p < 2; p++) {
            const int jt = wid * 2 + p;
            if (jt >= 15) continue;
            #pragma unroll
            for (int m = 0; m < 4; m++) {
                wmma::store_matrix_sync(slab +  0, acc[p][0][m], 52, wmma::mem_row_major);
                wmma::store_matrix_sync(slab + 16, acc[p][1][m], 52, wmma::mem_row_major);
                wmma::store_matrix_sync(slab + 32, acc[p][2][m], 52, wmma::mem_row_major);
                __syncwarp();
                #pragma unroll
                for (int e = 0; e < 8; e++) {
                    int idx = e * 32 + lane;
                    int rr = idx >> 4, cc = idx & 15;
                    int j = jt * 16 + cc;
                    if (j < cH) {
                        int bl = m * 16 + rr;
                        int b = b0 + bl;
                        const float* xrow = xg + ((size_t)t * cB + b) * c3H;
                        float hgr = slab[rr * 52 + cc];
                        float hgz = slab[rr * 52 + 16 + cc];
                        float hgn = slab[rr * 52 + 32 + cc];
                        float r = sigmoidf(xrow[j]          + hgr + bhh[j]);
                        float z = sigmoidf(xrow[cH + j]     + hgz + bhh[cH + j]);
                        float n = tanhf(xrow[2 * cH + j] + r * (hgn + bhh[2 * cH + j]));
                        float hold = hex[bl * cHS + j];
                        float h2 = (1.f - z) * n + z * hold;
                        hex[bl * cHS + j] = h2;
                        hs[bl * cHS + j] = to_tf32(h2);
                        g_out[((size_t)t * cB + b) * c2H + dir * cH + j] = h2;
                    }
                }
                __syncwarp();
            }
        }
        __syncthreads();   // hs(t+1) ready before next step's mma reads it
    }
}

// ---------------------------------------------------------------------------
// small kernels
// ---------------------------------------------------------------------------
__global__ void rowdot_sent_kernel(const float* __restrict__ proj) {
    int row = blockIdx.x * 8 + (threadIdx.x >> 5);
    if (row >= cB) return;
    int lane = threadIdx.x & 31;
    const float* u = g_u2 + (size_t)row * c2H;
    float s = 0.f;
    for (int j = lane; j < c2H; j += 32) s += u[j] * proj[j];
    #pragma unroll
    for (int o = 16; o; o >>= 1) s += __shfl_xor_sync(0xffffffffu, s, o);
    if (lane == 0) g_s2[row] = s;
}

__global__ void softmaxT_kernel() {
    int b = blockIdx.x * 8 + (threadIdx.x >> 5);
    int lane = threadIdx.x & 31;
    const float* p0 = g_scorep + ((size_t)lane * cB + b) * 4;
    const float* p1 = g_scorep + ((size_t)(lane + 32) * cB + b) * 4;
    float v0 = 0.f, v1 = 0.f;
    #pragma unroll
    for (int i = 0; i < 4; i++) { v0 += p0[i]; v1 += p1[i]; }
    float m = fmaxf(v0, v1);
    #pragma unroll
    for (int o = 16; o; o >>= 1) m = fmaxf(m, __shfl_xor_sync(0xffffffffu, m, o));
    float e0 = expf(v0 - m), e1 = expf(v1 - m);
    float sum = e0 + e1;
    #pragma unroll
    for (int o = 16; o; o >>= 1) sum += __shfl_xor_sync(0xffffffffu, sum, o);
    float inv = 1.f / sum;
    g_alpha[(size_t)b * cT + lane] = e0 * inv;
    g_alpha[(size_t)b * cT + lane + 32] = e1 * inv;
}

__global__ void wordvec_kernel() {
    int b = blockIdx.y;
    int h = blockIdx.x * 128 + threadIdx.x;
    if (h >= c2H) return;
    const float* al = g_alpha + (size_t)b * cT;
    float s = 0.f;
    for (int t = 0; t < cT; t++)
        s += al[t] * g_out[((size_t)t * cB + b) * c2H + h];
    g_wv[(size_t)b * c2H + h] = s;
}

__global__ void sentvec_kernel() {
    int nb = blockIdx.x;
    __shared__ float beta[cMS];
    if (threadIdx.x == 0) {
        float v[cMS];
        float m = -1e30f;
        for (int ms = 0; ms < cMS; ms++) { v[ms] = g_s2[nb * cMS + ms]; m = fmaxf(m, v[ms]); }
        float sum = 0.f;
        for (int ms = 0; ms < cMS; ms++) { v[ms] = expf(v[ms] - m); sum += v[ms]; }
        float inv = 1.f / sum;
        for (int ms = 0; ms < cMS; ms++) beta[ms] = v[ms] * inv;
    }
    __syncthreads();
    for (int h = threadIdx.x; h < c2H; h += blockDim.x) {
        float s = 0.f;
        #pragma unroll
        for (int ms = 0; ms < cMS; ms++)
            s += beta[ms] * g_wv[((size_t)nb * cMS + ms) * c2H + h];
        g_sent[(size_t)nb * c2H + h] = s;
    }
}

__global__ void fc_scatter_kernel(const float* __restrict__ fcW,
                                  const float* __restrict__ fcb,
                                  const int* __restrict__ pairs,
                                  float* __restrict__ out)
{
    int nb = blockIdx.x;
    __shared__ float sv[c2H];
    for (int k = threadIdx.x; k < c2H; k += blockDim.x)
        sv[k] = g_sent[(size_t)nb * c2H + k];
    __syncthreads();
    int o = threadIdx.x;
    if (o < cOUT) {
        const float* w = fcW + (size_t)o * c2H;
        float s = fcb[o];
        for (int k = 0; k < c2H; k++) s += sv[k] * w[k];
        int d  = pairs[nb * 3 + 0];
        int e1 = pairs[nb * 3 + 1];
        int e2 = pairs[nb * 3 + 2];
        out[(((size_t)d * cENT + e1) * cENT + e2) * cOUT + o] = s;
    }
}

// ---------------------------------------------------------------------------
extern "C" void kernel_launch(void* const* d_in, const int* in_sizes, int n_in,
                              void* d_out, int out_size) {
    const float* bag   = (const float*)d_in[0];
    const float* Wihf  = (const float*)d_in[1];
    const float* Whhf  = (const float*)d_in[2];
    const float* bihf  = (const float*)d_in[3];
    const float* bhhf  = (const float*)d_in[4];
    const float* Wihr  = (const float*)d_in[5];
    const float* Whhr  = (const float*)d_in[6];
    const float* bihr  = (const float*)d_in[7];
    const float* bhhr  = (const float*)d_in[8];
    const float* Wword = (const float*)d_in[9];
    const float* bword = (const float*)d_in[10];
    const float* pjw   = (const float*)d_in[11];
    const float* Wsent = (const float*)d_in[12];
    const float* bsent = (const float*)d_in[13];
    const float* pjs   = (const float*)d_in[14];
    const float* fcW   = (const float*)d_in[15];
    const float* fcb   = (const float*)d_in[16];
    const int*   pairs = (const int*)d_in[17];
    float* out = (float*)d_out;

    static int attr_done = 0;
    if (!attr_done) {
        cudaFuncSetAttribute(iproj_kernel, cudaFuncAttributeMaxDynamicSharedMemorySize, IP_SMEM);
        cudaFuncSetAttribute(attn_gemm_kernel<2>, cudaFuncAttributeMaxDynamicSharedMemorySize, AT_SMEM);
        cudaFuncSetAttribute(attn_gemm_kernel<3>, cudaFuncAttributeMaxDynamicSharedMemorySize, AT_SMEM);
        cudaFuncSetAttribute(gru_persistent_kernel, cudaFuncAttributeMaxDynamicSharedMemorySize, GRU_SMEM);
        attr_done = 1;
    }

    zero_out_kernel<<<(out_size + 255) / 256, 256>>>(out, out_size);
    wt_prep_kernel<<<(2 * NCHK * 8 * cWS + 255) / 256, 256>>>(Whhf, Whhr);
    wih2_prep_kernel<<<(2 * 6 * 12 * 128 * 36 + 255) / 256, 256>>>(Wihf, Wihr);
    wat_prep_kernel<<<(2 * 4 * 15 * 32 * 132 + 255) / 256, 256>>>(Wword, Wsent);

    // input projections (both dirs)
    {
        dim3 grid((c3H + 127) / 128, (int)(cTB / 128), 2);
        iproj_kernel<<<grid, 256, IP_SMEM>>>(bag, bihf, bihr);
    }

    // GRU recurrence: single persistent launch, 128 CTAs = one wave
    {
        dim3 grid(cB / BT, 2);
        gru_persistent_kernel<<<grid, 256, GRU_SMEM>>>(bhhf, bhhr);
    }

    // word attention (scores fused; no u materialized)
    {
        dim3 grid((c2H + 127) / 128, (int)(cTB / 128));
        attn_gemm_kernel<2><<<grid, 256, AT_SMEM>>>(bword, pjw);
    }
    softmaxT_kernel<<<cB / 8, 256>>>();
    {
        dim3 grid((c2H + 127) / 128, cB);
        wordvec_kernel<<<grid, 128>>>();
    }

    // sentence attention
    {
        dim3 grid((c2H + 127) / 128, cB / 128);
        attn_gemm_kernel<3><<<grid, 256, AT_SMEM>>>(bsent, nullptr);
    }
    rowdot_sent_kernel<<<cB / 8, 256>>>(pjs);
    sentvec_kernel<<<cNB, 128>>>();

    fc_scatter_kernel<<<cNB, 64>>>(fcW, fcb, pairs, out);
}